// round 13
// baseline (speedup 1.0000x reference)
#include <cuda_runtime.h>
#include <cuda_bf16.h>
#include <cuda_fp16.h>
#include <cstdint>

#define NN   10000
#define NPAD 10048          // 157*64
#define PP   4
#define EE   160000
#define INF_ 256
#define HH   8
#define DD   64
#define HD_  512
#define NEG_SLOPE 0.2f

// ---------------- device scratch ----------------
__device__ __half g_Whh[(size_t)PP * NN * HD_];   // fp16 Wh (gather input)
__device__ __half g_zh[(size_t)PP * NN * HD_];    // fp16 z (gather output)
__device__ float g_el[(size_t)PP * NN * HH];
__device__ float g_er[(size_t)PP * NN * HH];
__device__ int   g_cnt[PP * NN];
__device__ int   g_off[PP * NN];
__device__ int   g_pos[PP * NN];
__device__ int   g_sperm[(size_t)PP * EE];
__device__ __nv_bfloat16 g_h_hi[(size_t)NPAD * INF_];   // pad rows stay zero
__device__ __nv_bfloat16 g_h_lo[(size_t)NPAD * INF_];
__device__ __nv_bfloat16 g_W_hi[(size_t)PP * HD_ * INF_];  // [p][n][k]
__device__ __nv_bfloat16 g_W_lo[(size_t)PP * HD_ * INF_];
__device__ float g_w [PP];
__device__ float g_beta[PP];

// ---------------- K0 ----------------
__global__ void k_zero() {
    int i = blockIdx.x * blockDim.x + threadIdx.x;
    if (i < PP * NN) g_cnt[i] = 0;
    if (i < PP) g_w[i] = 0.f;
}

// ---------------- convert h to bf16 hi/lo ----------------
__global__ void k_cvt_h(const float* __restrict__ h) {
    int i = blockIdx.x * blockDim.x + threadIdx.x;
    if (i < NN * INF_) {
        float v = h[i];
        __nv_bfloat16 hi = __float2bfloat16(v);
        g_h_hi[i] = hi;
        g_h_lo[i] = __float2bfloat16(v - __bfloat162float(hi));
    }
}

// ---------------- convert + transpose W ----------------
__global__ void k_cvt_W(const float* __restrict__ W) {
    __shared__ float tile[32][33];
    int p  = blockIdx.z;
    int k0 = blockIdx.x * 32;
    int n0 = blockIdx.y * 32;
    int tx = threadIdx.x, ty0 = threadIdx.y;
    for (int ty = ty0; ty < 32; ty += 8)
        tile[ty][tx] = W[(size_t)p * INF_ * HD_ + (size_t)(k0 + ty) * HD_ + n0 + tx];
    __syncthreads();
    for (int ty = ty0; ty < 32; ty += 8) {
        float v = tile[tx][ty];
        __nv_bfloat16 hi = __float2bfloat16(v);
        size_t oi = (size_t)p * HD_ * INF_ + (size_t)(n0 + ty) * INF_ + k0 + tx;
        g_W_hi[oi] = hi;
        g_W_lo[oi] = __float2bfloat16(v - __bfloat162float(hi));
    }
}

// ---------------- gather math helpers ----------------
__device__ __forceinline__ void acc_h8(float* acc, uint4 u, float xv) {
    float2 f0 = __half22float2(*(__half2*)&u.x);
    float2 f1 = __half22float2(*(__half2*)&u.y);
    float2 f2 = __half22float2(*(__half2*)&u.z);
    float2 f3 = __half22float2(*(__half2*)&u.w);
    acc[0] += xv * f0.x;  acc[1] += xv * f0.y;
    acc[2] += xv * f1.x;  acc[3] += xv * f1.y;
    acc[4] += xv * f2.x;  acc[5] += xv * f2.y;
    acc[6] += xv * f3.x;  acc[7] += xv * f3.y;
}
__device__ __forceinline__ float edge_exp(float el, float erd) {
    float v = el + erd;
    v = v > 0.f ? v : NEG_SLOPE * v;
    return expf(v);       // shift-free softmax (safe range)
}
__device__ __forceinline__ uint4 pack_h8(const float* o) {
    uint4 r;
    *(__half2*)&r.x = __floats2half2_rn(o[0], o[1]);
    *(__half2*)&r.y = __floats2half2_rn(o[2], o[3]);
    *(__half2*)&r.z = __floats2half2_rn(o[4], o[5]);
    *(__half2*)&r.w = __floats2half2_rn(o[6], o[7]);
    return r;
}

// ---------------- PROBE: gather-mimic, deterministic synthetic CSR ----------------
// Same access pattern as k_gather (random 1KB fp16 rows + random 32B el sectors),
// path 0 only, fixed deg=16, hashed src ids. Output overwritten by real gather.
__global__ __launch_bounds__(256) void k_probe() {
    int lane = threadIdx.x & 31;
    int d = blockIdx.x * 8 + (threadIdx.x >> 5);
    if (d >= NN) return;
    int head = lane >> 2;
    const float*  elb = &g_el[head];
    const __half* whb = &g_Whh[lane * 16];
    float erd = g_er[(size_t)d * HH + head];

    float acc[16];
    #pragma unroll
    for (int q = 0; q < 16; q++) acc[q] = 0.f;
    float ssum = 0.f;

    for (int j = 0; j < 16; j += 4) {
        int s[4];
        #pragma unroll
        for (int u = 0; u < 4; u++)
            s[u] = (int)(((unsigned)d * 1103515245u + (unsigned)(j + u) * 2654435761u) % NN);
        float e[4];
        #pragma unroll
        for (int u = 0; u < 4; u++) e[u] = elb[(size_t)s[u] * HH];
        uint4 lo[4], hi[4];
        #pragma unroll
        for (int u = 0; u < 4; u++) {
            const uint4* R = (const uint4*)&whb[(size_t)s[u] * HD_];
            lo[u] = R[0];
            hi[u] = R[1];
        }
        #pragma unroll
        for (int u = 0; u < 4; u++) {
            float xv = edge_exp(e[u], erd);
            ssum += xv;
            acc_h8(acc,     lo[u], xv);
            acc_h8(acc + 8, hi[u], xv);
        }
    }
    float inv = (ssum > 0.f) ? 1.f / ssum : 0.f;
    #pragma unroll
    for (int q = 0; q < 16; q++) acc[q] *= inv;
    uint4* dst = (uint4*)&g_zh[(size_t)d * HD_ + lane * 16];
    __stcs(dst,     pack_h8(acc));
    __stcs(dst + 1, pack_h8(acc + 8));
}

// ---------------- mma / ldmatrix helpers ----------------
__device__ __forceinline__ void mma_bf16(float& c0, float& c1, float& c2, float& c3,
                                         uint32_t a0, uint32_t a1, uint32_t a2, uint32_t a3,
                                         uint32_t b0, uint32_t b1) {
    asm volatile("mma.sync.aligned.m16n8k16.row.col.f32.bf16.bf16.f32 "
                 "{%0,%1,%2,%3}, {%4,%5,%6,%7}, {%8,%9}, {%0,%1,%2,%3};"
                 : "+f"(c0), "+f"(c1), "+f"(c2), "+f"(c3)
                 : "r"(a0), "r"(a1), "r"(a2), "r"(a3), "r"(b0), "r"(b1));
}
__device__ __forceinline__ void ldsm4(uint32_t* r, const void* ptr) {
    uint32_t a = (uint32_t)__cvta_generic_to_shared(ptr);
    asm volatile("ldmatrix.sync.aligned.m8n8.x4.shared.b16 {%0,%1,%2,%3}, [%4];"
                 : "=r"(r[0]), "=r"(r[1]), "=r"(r[2]), "=r"(r[3]) : "r"(a));
}

// ---------------- K1: Wh = h @ W[p] (bf16 hi/lo 3-term) + fused el/er ----------------
__global__ __launch_bounds__(256) void k_gemm(const float* __restrict__ al,
                                              const float* __restrict__ ar) {
    __shared__ __nv_bfloat16 As_hi[64][40];
    __shared__ __nv_bfloat16 As_lo[64][40];
    __shared__ __nv_bfloat16 Bs_hi[128][40];
    __shared__ __nv_bfloat16 Bs_lo[128][40];
    __shared__ float s_att[64][2][2];

    int p  = blockIdx.z;
    int m0 = blockIdx.x * 64;
    int n0 = blockIdx.y * 128;
    int t    = threadIdx.x;
    int lane = t & 31;
    int w    = t >> 5;
    int warp_m = (w & 1) * 32;
    int warp_n = (w >> 1) * 32;
    int g   = lane >> 2;
    int tid = lane & 3;
    int lm_r = lane & 15;
    int lm_c = (lane >> 4) * 8;

    float acc[2][4][4];
    #pragma unroll
    for (int mt = 0; mt < 2; mt++)
        #pragma unroll
        for (int nt = 0; nt < 4; nt++)
            #pragma unroll
            for (int q = 0; q < 4; q++) acc[mt][nt][q] = 0.f;

    int a_row  = t >> 2;
    int a_koff = (t & 3) * 8;
    const __nv_bfloat16* ah_base  = &g_h_hi[(size_t)(m0 + a_row) * INF_ + a_koff];
    const __nv_bfloat16* alo_base = &g_h_lo[(size_t)(m0 + a_row) * INF_ + a_koff];
    int b_n0 = t >> 2;
    int b_k0 = (t & 3) * 8;
    int b_n1 = (t + 256) >> 2;
    int b_k1 = ((t + 256) & 3) * 8;
    const __nv_bfloat16* bW  = &g_W_hi[(size_t)p * HD_ * INF_ + (size_t)n0 * INF_];
    const __nv_bfloat16* bWl = &g_W_lo[(size_t)p * HD_ * INF_ + (size_t)n0 * INF_];

    uint4 pa_hi, pa_lo, pb_hi0, pb_hi1, pb_lo0, pb_lo1;
    pa_hi  = *(const uint4*)&ah_base[0];
    pa_lo  = *(const uint4*)&alo_base[0];
    pb_hi0 = *(const uint4*)&bW [(size_t)b_n0 * INF_ + b_k0];
    pb_hi1 = *(const uint4*)&bW [(size_t)b_n1 * INF_ + b_k1];
    pb_lo0 = *(const uint4*)&bWl[(size_t)b_n0 * INF_ + b_k0];
    pb_lo1 = *(const uint4*)&bWl[(size_t)b_n1 * INF_ + b_k1];

    for (int kb = 0; kb < 8; kb++) {
        __syncthreads();
        *(uint4*)&As_hi[a_row][a_koff] = pa_hi;
        *(uint4*)&As_lo[a_row][a_koff] = pa_lo;
        *(uint4*)&Bs_hi[b_n0][b_k0]    = pb_hi0;
        *(uint4*)&Bs_hi[b_n1][b_k1]    = pb_hi1;
        *(uint4*)&Bs_lo[b_n0][b_k0]    = pb_lo0;
        *(uint4*)&Bs_lo[b_n1][b_k1]    = pb_lo1;
        __syncthreads();
        if (kb < 7) {
            int kk = (kb + 1) * 32;
            pa_hi  = *(const uint4*)&ah_base[kk];
            pa_lo  = *(const uint4*)&alo_base[kk];
            pb_hi0 = *(const uint4*)&bW [(size_t)b_n0 * INF_ + kk + b_k0];
            pb_hi1 = *(const uint4*)&bW [(size_t)b_n1 * INF_ + kk + b_k1];
            pb_lo0 = *(const uint4*)&bWl[(size_t)b_n0 * INF_ + kk + b_k0];
            pb_lo1 = *(const uint4*)&bWl[(size_t)b_n1 * INF_ + kk + b_k1];
        }
        #pragma unroll
        for (int ks = 0; ks < 32; ks += 16) {
            uint32_t ah[2][4], al2[2][4], bh[2][4], bl2[2][4];
            #pragma unroll
            for (int mt = 0; mt < 2; mt++) {
                ldsm4(ah[mt],  &As_hi[warp_m + mt * 16 + lm_r][ks + lm_c]);
                ldsm4(al2[mt], &As_lo[warp_m + mt * 16 + lm_r][ks + lm_c]);
            }
            #pragma unroll
            for (int pr = 0; pr < 2; pr++) {
                ldsm4(bh[pr],  &Bs_hi[warp_n + pr * 16 + lm_r][ks + lm_c]);
                ldsm4(bl2[pr], &Bs_lo[warp_n + pr * 16 + lm_r][ks + lm_c]);
            }
            #pragma unroll
            for (int mt = 0; mt < 2; mt++)
                #pragma unroll
                for (int nt = 0; nt < 4; nt++) {
                    int pr = nt >> 1, o = nt & 1;
                    float* c = acc[mt][nt];
                    mma_bf16(c[0], c[1], c[2], c[3],
                             ah[mt][0], ah[mt][1], ah[mt][2], ah[mt][3],
                             bh[pr][o], bh[pr][o + 2]);
                    mma_bf16(c[0], c[1], c[2], c[3],
                             ah[mt][0], ah[mt][1], ah[mt][2], ah[mt][3],
                             bl2[pr][o], bl2[pr][o + 2]);
                    mma_bf16(c[0], c[1], c[2], c[3],
                             al2[mt][0], al2[mt][1], al2[mt][2], al2[mt][3],
                             bh[pr][o], bh[pr][o + 2]);
                }
        }
    }

    // ---- store Wh as fp16 ----
    #pragma unroll
    for (int mt = 0; mt < 2; mt++) {
        int r0 = m0 + warp_m + mt * 16 + g;
        int r1 = r0 + 8;
        #pragma unroll
        for (int nt = 0; nt < 4; nt++) {
            int c = n0 + warp_n + nt * 8 + tid * 2;
            if (r0 < NN)
                *(__half2*)&g_Whh[((size_t)p * NN + r0) * HD_ + c] =
                    __floats2half2_rn(acc[mt][nt][0], acc[mt][nt][1]);
            if (r1 < NN)
                *(__half2*)&g_Whh[((size_t)p * NN + r1) * HD_ + c] =
                    __floats2half2_rn(acc[mt][nt][2], acc[mt][nt][3]);
        }
    }

    // ---- fused attention dot-products ----
    int head0 = n0 >> 6;
    int hw = warp_n >= 64;
    int dbase = (warp_n & 32);
    const float* alp = &al[((size_t)p * HH + head0 + hw) * DD];
    const float* arp = &ar[((size_t)p * HH + head0 + hw) * DD];

    s_att[t >> 2][(t >> 1) & 1][t & 1] = 0.f;
    __syncthreads();

    #pragma unroll
    for (int mt = 0; mt < 2; mt++) {
        #pragma unroll
        for (int rr = 0; rr < 2; rr++) {
            float pel = 0.f, per_ = 0.f;
            #pragma unroll
            for (int nt = 0; nt < 4; nt++) {
                #pragma unroll
                for (int j = 0; j < 2; j++) {
                    float c = acc[mt][nt][rr * 2 + j];
                    int dd = dbase + nt * 8 + tid * 2 + j;
                    pel  += c * alp[dd];
                    per_ += c * arp[dd];
                }
            }
            pel  += __shfl_xor_sync(~0u, pel, 1);  pel  += __shfl_xor_sync(~0u, pel, 2);
            per_ += __shfl_xor_sync(~0u, per_, 1); per_ += __shfl_xor_sync(~0u, per_, 2);
            if (tid == 0) {
                int row = warp_m + mt * 16 + g + rr * 8;
                atomicAdd(&s_att[row][hw][0], pel);
                atomicAdd(&s_att[row][hw][1], per_);
            }
        }
    }
    __syncthreads();
    {
        int row = t >> 2, h2 = (t >> 1) & 1, lr = t & 1;
        int gr = m0 + row;
        if (gr < NN) {
            float v = s_att[row][h2][lr];
            size_t idx = ((size_t)p * NN + gr) * HH + head0 + h2;
            if (lr == 0) g_el[idx] = v; else g_er[idx] = v;
        }
    }
}

// ---------------- CSR build ----------------
__global__ void k_count(const int* __restrict__ edst) {
    int e = blockIdx.x * blockDim.x + threadIdx.x;
    int p = blockIdx.y;
    atomicAdd(&g_cnt[p * NN + edst[(size_t)p * EE + e]], 1);
}

__global__ __launch_bounds__(1024) void k_scan() {
    __shared__ int part[1024];
    int p = blockIdx.x;
    int t = threadIdx.x;
    const int CH = 10;
    int b = t * CH;
    int loc[CH];
    int sum = 0;
    #pragma unroll
    for (int i = 0; i < CH; i++) {
        int idx = b + i;
        int v = (idx < NN) ? g_cnt[p * NN + idx] : 0;
        loc[i] = sum;
        sum += v;
    }
    part[t] = sum;
    __syncthreads();
    for (int ofs = 1; ofs < 1024; ofs <<= 1) {
        int val = (t >= ofs) ? part[t - ofs] : 0;
        __syncthreads();
        part[t] += val;
        __syncthreads();
    }
    int ex = part[t] - sum;
    #pragma unroll
    for (int i = 0; i < CH; i++) {
        int idx = b + i;
        if (idx < NN) {
            int o = ex + loc[i];
            g_off[p * NN + idx] = o;
            g_pos[p * NN + idx] = o;
        }
    }
}

__global__ void k_scatter(const int* __restrict__ esrc, const int* __restrict__ edst) {
    int e = blockIdx.x * blockDim.x + threadIdx.x;
    int p = blockIdx.y;
    int d = edst[(size_t)p * EE + e];
    int s = esrc[(size_t)p * EE + e];
    int pos = atomicAdd(&g_pos[p * NN + d], 1);
    g_sperm[(size_t)p * EE + pos] = s;
}

// ---------------- K4: gather, fused softmax, fp16 in/out ----------------
__global__ __launch_bounds__(256) void k_gather(const float* __restrict__ gb) {
    int lane = threadIdx.x & 31;
    int d = blockIdx.x * 8 + (threadIdx.x >> 5);
    if (d >= NN) return;                       // OOB guard (bug fix)
    int p = blockIdx.y;
    int head = lane >> 2;

    int start = g_off[p * NN + d];
    int deg   = g_cnt[p * NN + d];
    const int*    sp  = &g_sperm[(size_t)p * EE + start];
    const float*  elb = &g_el[(size_t)p * NN * HH + head];
    const __half* whb = &g_Whh[(size_t)p * NN * HD_ + lane * 16];
    float erd = g_er[((size_t)p * NN + d) * HH + head];

    float acc[16];
    #pragma unroll
    for (int q = 0; q < 16; q++) acc[q] = 0.f;
    float ssum = 0.f;

    int j = 0;
    for (; j + 3 < deg; j += 4) {
        int s[4];
        #pragma unroll
        for (int u = 0; u < 4; u++) s[u] = sp[j + u];
        float e[4];
        #pragma unroll
        for (int u = 0; u < 4; u++) e[u] = elb[(size_t)s[u] * HH];
        uint4 lo[4], hi[4];
        #pragma unroll
        for (int u = 0; u < 4; u++) {
            const uint4* R = (const uint4*)&whb[(size_t)s[u] * HD_];
            lo[u] = R[0];
            hi[u] = R[1];
        }
        #pragma unroll
        for (int u = 0; u < 4; u++) {
            float xv = edge_exp(e[u], erd);
            ssum += xv;
            acc_h8(acc,     lo[u], xv);
            acc_h8(acc + 8, hi[u], xv);
        }
    }
    for (; j < deg; j++) {
        int s0 = sp[j];
        float xv = edge_exp(elb[(size_t)s0 * HH], erd);
        const uint4* R = (const uint4*)&whb[(size_t)s0 * HD_];
        uint4 a0 = R[0], a1 = R[1];
        ssum += xv;
        acc_h8(acc, a0, xv);  acc_h8(acc + 8, a1, xv);
    }

    float inv = (ssum > 0.f) ? 1.f / ssum : 0.f;
    const float* bp = &gb[p * HD_ + lane * 16];
    float o[16];
    #pragma unroll
    for (int q = 0; q < 4; q++) {
        float4 b4 = *(const float4*)&bp[q * 4];
        o[4*q+0] = acc[4*q+0] * inv + b4.x;
        o[4*q+1] = acc[4*q+1] * inv + b4.y;
        o[4*q+2] = acc[4*q+2] * inv + b4.z;
        o[4*q+3] = acc[4*q+3] * inv + b4.w;
    }
    #pragma unroll
    for (int q = 0; q < 16; q++) o[q] = o[q] > 0.f ? o[q] : expm1f(o[q]);
    uint4* dst = (uint4*)&g_zh[((size_t)p * NN + d) * HD_ + lane * 16];
    __stcs(dst,     pack_h8(o));
    __stcs(dst + 1, pack_h8(o + 8));
}

// ---------------- K5: semantic partial (fp16 z reads, float4 smem) ----------------
#define POST_NB 32
#define W1T_LD 68
#define POST_SMEM ((POST_NB * HD_ + 64 * W1T_LD + 256) * sizeof(float))
__global__ __launch_bounds__(256) void k_post(const float* __restrict__ W1,
                                              const float* __restrict__ b1,
                                              const float* __restrict__ W2) {
    extern __shared__ float dsm[];
    float* zs  = dsm;                       // 32*512
    float* w1t = dsm + POST_NB * HD_;       // [j][k] 64 x 68
    float* red = w1t + 64 * W1T_LD;         // 256
    int p  = blockIdx.y;
    int n0 = blockIdx.x * POST_NB;
    int t  = threadIdx.x;
    for (int i = t; i < POST_NB * HD_ / 8; i += 256) {
        int node = i >> 6, c8 = (i & 63) * 8;
        int gn = n0 + node;
        if (gn < NN) {
            uint4 u = *(const uint4*)&g_zh[((size_t)p * NN + gn) * HD_ + c8];
            float2 f0 = __half22float2(*(__half2*)&u.x);
            float2 f1 = __half22float2(*(__half2*)&u.y);
            float2 f2 = __half22float2(*(__half2*)&u.z);
            float2 f3 = __half22float2(*(__half2*)&u.w);
            *(float4*)&zs[node * HD_ + c8]     = make_float4(f0.x, f0.y, f1.x, f1.y);
            *(float4*)&zs[node * HD_ + c8 + 4] = make_float4(f2.x, f2.y, f3.x, f3.y);
        } else {
            *(float4*)&zs[node * HD_ + c8]     = make_float4(0.f, 0.f, 0.f, 0.f);
            *(float4*)&zs[node * HD_ + c8 + 4] = make_float4(0.f, 0.f, 0.f, 0.f);
        }
    }
    __syncthreads();
    int j = t & 63, grp = t >> 6;
    float acc[8];
    #pragma unroll
    for (int u = 0; u < 8; u++) acc[u] = 0.f;
    for (int kc = 0; kc < 8; kc++) {
        for (int i = t; i < 4096; i += 256) {
            int k = i >> 6, jj = i & 63;
            w1t[jj * W1T_LD + k] = W1[(size_t)(kc * 64 + k) * 64 + jj];
        }
        __syncthreads();
        #pragma unroll 4
        for (int k4 = 0; k4 < 64; k4 += 4) {
            float4 wv = *(const float4*)&w1t[j * W1T_LD + k4];
            int zb = kc * 64 + k4;
            #pragma unroll
            for (int u = 0; u < 8; u++) {
                float4 zv = *(const float4*)&zs[(grp * 8 + u) * HD_ + zb];
                acc[u] += zv.x * wv.x + zv.y * wv.y + zv.z * wv.z + zv.w * wv.w;
            }
        }
        __syncthreads();
    }
    float b = b1[j], w2 = W2[j];
    float contrib = 0.f;
    #pragma unroll
    for (int u = 0; u < 8; u++) {
        int gn = n0 + grp * 8 + u;
        if (gn < NN) contrib += tanhf(acc[u] + b) * w2;
    }
    red[t] = contrib;
    __syncthreads();
    for (int ofs = 128; ofs > 0; ofs >>= 1) {
        if (t < ofs) red[t] += red[t + ofs];
        __syncthreads();
    }
    if (t == 0) atomicAdd(&g_w[p], red[0]);
}

// ---------------- K6: beta ----------------
__global__ void k_beta() {
    if (threadIdx.x == 0) {
        float w[PP], m = -1e30f;
        #pragma unroll
        for (int p = 0; p < PP; p++) { w[p] = g_w[p] / (float)NN; m = fmaxf(m, w[p]); }
        float s = 0.f;
        #pragma unroll
        for (int p = 0; p < PP; p++) { w[p] = expf(w[p] - m); s += w[p]; }
        #pragma unroll
        for (int p = 0; p < PP; p++) g_beta[p] = w[p] / s;
    }
}

// ---------------- K7: combine (fp16 z reads) ----------------
__global__ void k_comb(float* __restrict__ out) {
    int i = blockIdx.x * blockDim.x + threadIdx.x;   // 8-elem chunk index
    const size_t stride = (size_t)NN * HD_;
    float bw[PP] = {g_beta[0], g_beta[1], g_beta[2], g_beta[3]};
    float o[8] = {0,0,0,0,0,0,0,0};
    #pragma unroll
    for (int p = 0; p < PP; p++) {
        uint4 u = *(const uint4*)&g_zh[p * stride + (size_t)i * 8];
        float2 f0 = __half22float2(*(__half2*)&u.x);
        float2 f1 = __half22float2(*(__half2*)&u.y);
        float2 f2 = __half22float2(*(__half2*)&u.z);
        float2 f3 = __half22float2(*(__half2*)&u.w);
        o[0] += bw[p] * f0.x;  o[1] += bw[p] * f0.y;
        o[2] += bw[p] * f1.x;  o[3] += bw[p] * f1.y;
        o[4] += bw[p] * f2.x;  o[5] += bw[p] * f2.y;
        o[6] += bw[p] * f3.x;  o[7] += bw[p] * f3.y;
    }
    *(float4*)&out[(size_t)i * 8]     = make_float4(o[0], o[1], o[2], o[3]);
    *(float4*)&out[(size_t)i * 8 + 4] = make_float4(o[4], o[5], o[6], o[7]);
}

// ---------------- launcher ----------------
extern "C" void kernel_launch(void* const* d_in, const int* in_sizes, int n_in,
                              void* d_out, int out_size) {
    const float* h     = (const float*)d_in[0];
    const int*   esrc  = (const int*)  d_in[1];
    const int*   edst  = (const int*)  d_in[2];
    const float* gat_W = (const float*)d_in[3];
    const float* al    = (const float*)d_in[4];
    const float* ar    = (const float*)d_in[5];
    const float* gat_b = (const float*)d_in[6];
    const float* sW1   = (const float*)d_in[7];
    const float* sb1   = (const float*)d_in[8];
    const float* sW2   = (const float*)d_in[9];
    float* out = (float*)d_out;

    cudaFuncSetAttribute(k_post, cudaFuncAttributeMaxDynamicSharedMemorySize,
                         (int)POST_SMEM);

    k_zero<<<(PP * NN + 255) / 256, 256>>>();
    k_cvt_h<<<(NN * INF_ + 255) / 256, 256>>>(h);
    dim3 gw(INF_ / 32, HD_ / 32, PP);
    k_cvt_W<<<gw, dim3(32, 8)>>>(gat_W);

    // launch #4 — gather-pattern probe for ncu (output overwritten by real gather)
    k_probe<<<(NN + 7) / 8, 256>>>();

    dim3 ge(EE / 256, PP);
    k_count<<<ge, 256>>>(edst);
    k_scan<<<PP, 1024>>>();
    k_scatter<<<ge, 256>>>(esrc, edst);

    dim3 gg((NN + 63) / 64, HD_ / 128, PP);
    k_gemm<<<gg, 256>>>(al, ar);

    dim3 gga((NN + 7) / 8, PP);
    k_gather<<<gga, 256>>>(gat_b);

    dim3 gp((NN + POST_NB - 1) / POST_NB, PP);
    k_post<<<gp, 256, POST_SMEM>>>(sW1, sb1, sW2);

    k_beta<<<1, 32>>>();

    k_comb<<<(NN * HD_ / 8) / 256, 256>>>(out);
}

// round 15
// speedup vs baseline: 1.0340x; 1.0340x over previous
#include <cuda_runtime.h>
#include <cuda_bf16.h>
#include <cuda_fp16.h>
#include <cstdint>

#define NN   10000
#define NPAD 10048          // 157*64
#define PP   4
#define EE   160000
#define INF_ 256
#define HH   8
#define DD   64
#define HD_  512
#define NEG_SLOPE 0.2f

// ---------------- device scratch ----------------
__device__ __half g_Whh[(size_t)PP * NN * HD_];   // fp16 Wh (gather input)
__device__ __half g_zh[(size_t)PP * NN * HD_];    // fp16 z (gather output)
__device__ float g_el[(size_t)PP * NN * HH];
__device__ float g_er[(size_t)PP * NN * HH];
__device__ int   g_cnt[PP * NN];
__device__ int   g_off[PP * NN];
__device__ int   g_pos[PP * NN];
__device__ int   g_sperm[(size_t)PP * EE];
__device__ __nv_bfloat16 g_h_hi[(size_t)NPAD * INF_];   // pad rows stay zero
__device__ __nv_bfloat16 g_h_lo[(size_t)NPAD * INF_];
__device__ __nv_bfloat16 g_W_hi[(size_t)PP * HD_ * INF_];  // [p][n][k]
__device__ __nv_bfloat16 g_W_lo[(size_t)PP * HD_ * INF_];
__device__ float g_w [PP];
__device__ float g_beta[PP];

// ---------------- K0 ----------------
__global__ void k_zero() {
    int i = blockIdx.x * blockDim.x + threadIdx.x;
    if (i < PP * NN) g_cnt[i] = 0;
    if (i < PP) g_w[i] = 0.f;
}

// ---------------- convert h to bf16 hi/lo ----------------
__global__ void k_cvt_h(const float* __restrict__ h) {
    int i = blockIdx.x * blockDim.x + threadIdx.x;
    if (i < NN * INF_) {
        float v = h[i];
        __nv_bfloat16 hi = __float2bfloat16(v);
        g_h_hi[i] = hi;
        g_h_lo[i] = __float2bfloat16(v - __bfloat162float(hi));
    }
}

// ---------------- convert + transpose W ----------------
__global__ void k_cvt_W(const float* __restrict__ W) {
    __shared__ float tile[32][33];
    int p  = blockIdx.z;
    int k0 = blockIdx.x * 32;
    int n0 = blockIdx.y * 32;
    int tx = threadIdx.x, ty0 = threadIdx.y;
    for (int ty = ty0; ty < 32; ty += 8)
        tile[ty][tx] = W[(size_t)p * INF_ * HD_ + (size_t)(k0 + ty) * HD_ + n0 + tx];
    __syncthreads();
    for (int ty = ty0; ty < 32; ty += 8) {
        float v = tile[tx][ty];
        __nv_bfloat16 hi = __float2bfloat16(v);
        size_t oi = (size_t)p * HD_ * INF_ + (size_t)(n0 + ty) * INF_ + k0 + tx;
        g_W_hi[oi] = hi;
        g_W_lo[oi] = __float2bfloat16(v - __bfloat162float(hi));
    }
}

// ---------------- gather math helpers ----------------
__device__ __forceinline__ void acc_h8(float* acc, uint4 u, float xv) {
    float2 f0 = __half22float2(*(__half2*)&u.x);
    float2 f1 = __half22float2(*(__half2*)&u.y);
    float2 f2 = __half22float2(*(__half2*)&u.z);
    float2 f3 = __half22float2(*(__half2*)&u.w);
    acc[0] += xv * f0.x;  acc[1] += xv * f0.y;
    acc[2] += xv * f1.x;  acc[3] += xv * f1.y;
    acc[4] += xv * f2.x;  acc[5] += xv * f2.y;
    acc[6] += xv * f3.x;  acc[7] += xv * f3.y;
}
__device__ __forceinline__ float edge_exp(float el, float erd) {
    float v = el + erd;
    v = v > 0.f ? v : NEG_SLOPE * v;
    return expf(v);       // shift-free softmax (safe range)
}
__device__ __forceinline__ uint4 pack_h8(const float* o) {
    uint4 r;
    *(__half2*)&r.x = __floats2half2_rn(o[0], o[1]);
    *(__half2*)&r.y = __floats2half2_rn(o[2], o[3]);
    *(__half2*)&r.z = __floats2half2_rn(o[4], o[5]);
    *(__half2*)&r.w = __floats2half2_rn(o[6], o[7]);
    return r;
}

// ---------------- mma / ldmatrix helpers ----------------
__device__ __forceinline__ void mma_bf16(float& c0, float& c1, float& c2, float& c3,
                                         uint32_t a0, uint32_t a1, uint32_t a2, uint32_t a3,
                                         uint32_t b0, uint32_t b1) {
    asm volatile("mma.sync.aligned.m16n8k16.row.col.f32.bf16.bf16.f32 "
                 "{%0,%1,%2,%3}, {%4,%5,%6,%7}, {%8,%9}, {%0,%1,%2,%3};"
                 : "+f"(c0), "+f"(c1), "+f"(c2), "+f"(c3)
                 : "r"(a0), "r"(a1), "r"(a2), "r"(a3), "r"(b0), "r"(b1));
}
__device__ __forceinline__ void ldsm4(uint32_t* r, const void* ptr) {
    uint32_t a = (uint32_t)__cvta_generic_to_shared(ptr);
    asm volatile("ldmatrix.sync.aligned.m8n8.x4.shared.b16 {%0,%1,%2,%3}, [%4];"
                 : "=r"(r[0]), "=r"(r[1]), "=r"(r[2]), "=r"(r[3]) : "r"(a));
}

// ---------------- K1: Wh = h @ W[p] (bf16 hi/lo 3-term mma.sync) + fused el/er ------
__global__ __launch_bounds__(256) void k_gemm(const float* __restrict__ al,
                                              const float* __restrict__ ar) {
    __shared__ __nv_bfloat16 As_hi[64][40];
    __shared__ __nv_bfloat16 As_lo[64][40];
    __shared__ __nv_bfloat16 Bs_hi[128][40];
    __shared__ __nv_bfloat16 Bs_lo[128][40];
    __shared__ float s_att[64][2][2];

    int p  = blockIdx.z;
    int m0 = blockIdx.x * 64;
    int n0 = blockIdx.y * 128;
    int t    = threadIdx.x;
    int lane = t & 31;
    int w    = t >> 5;
    int warp_m = (w & 1) * 32;
    int warp_n = (w >> 1) * 32;
    int g   = lane >> 2;
    int tid = lane & 3;
    int lm_r = lane & 15;
    int lm_c = (lane >> 4) * 8;

    float acc[2][4][4];
    #pragma unroll
    for (int mt = 0; mt < 2; mt++)
        #pragma unroll
        for (int nt = 0; nt < 4; nt++)
            #pragma unroll
            for (int q = 0; q < 4; q++) acc[mt][nt][q] = 0.f;

    int a_row  = t >> 2;
    int a_koff = (t & 3) * 8;
    const __nv_bfloat16* ah_base  = &g_h_hi[(size_t)(m0 + a_row) * INF_ + a_koff];
    const __nv_bfloat16* alo_base = &g_h_lo[(size_t)(m0 + a_row) * INF_ + a_koff];
    int b_n0 = t >> 2;
    int b_k0 = (t & 3) * 8;
    int b_n1 = (t + 256) >> 2;
    int b_k1 = ((t + 256) & 3) * 8;
    const __nv_bfloat16* bW  = &g_W_hi[(size_t)p * HD_ * INF_ + (size_t)n0 * INF_];
    const __nv_bfloat16* bWl = &g_W_lo[(size_t)p * HD_ * INF_ + (size_t)n0 * INF_];

    uint4 pa_hi, pa_lo, pb_hi0, pb_hi1, pb_lo0, pb_lo1;
    pa_hi  = *(const uint4*)&ah_base[0];
    pa_lo  = *(const uint4*)&alo_base[0];
    pb_hi0 = *(const uint4*)&bW [(size_t)b_n0 * INF_ + b_k0];
    pb_hi1 = *(const uint4*)&bW [(size_t)b_n1 * INF_ + b_k1];
    pb_lo0 = *(const uint4*)&bWl[(size_t)b_n0 * INF_ + b_k0];
    pb_lo1 = *(const uint4*)&bWl[(size_t)b_n1 * INF_ + b_k1];

    for (int kb = 0; kb < 8; kb++) {
        __syncthreads();
        *(uint4*)&As_hi[a_row][a_koff] = pa_hi;
        *(uint4*)&As_lo[a_row][a_koff] = pa_lo;
        *(uint4*)&Bs_hi[b_n0][b_k0]    = pb_hi0;
        *(uint4*)&Bs_hi[b_n1][b_k1]    = pb_hi1;
        *(uint4*)&Bs_lo[b_n0][b_k0]    = pb_lo0;
        *(uint4*)&Bs_lo[b_n1][b_k1]    = pb_lo1;
        __syncthreads();
        if (kb < 7) {
            int kk = (kb + 1) * 32;
            pa_hi  = *(const uint4*)&ah_base[kk];
            pa_lo  = *(const uint4*)&alo_base[kk];
            pb_hi0 = *(const uint4*)&bW [(size_t)b_n0 * INF_ + kk + b_k0];
            pb_hi1 = *(const uint4*)&bW [(size_t)b_n1 * INF_ + kk + b_k1];
            pb_lo0 = *(const uint4*)&bWl[(size_t)b_n0 * INF_ + kk + b_k0];
            pb_lo1 = *(const uint4*)&bWl[(size_t)b_n1 * INF_ + kk + b_k1];
        }
        #pragma unroll
        for (int ks = 0; ks < 32; ks += 16) {
            uint32_t ah[2][4], al2[2][4], bh[2][4], bl2[2][4];
            #pragma unroll
            for (int mt = 0; mt < 2; mt++) {
                ldsm4(ah[mt],  &As_hi[warp_m + mt * 16 + lm_r][ks + lm_c]);
                ldsm4(al2[mt], &As_lo[warp_m + mt * 16 + lm_r][ks + lm_c]);
            }
            #pragma unroll
            for (int pr = 0; pr < 2; pr++) {
                ldsm4(bh[pr],  &Bs_hi[warp_n + pr * 16 + lm_r][ks + lm_c]);
                ldsm4(bl2[pr], &Bs_lo[warp_n + pr * 16 + lm_r][ks + lm_c]);
            }
            #pragma unroll
            for (int mt = 0; mt < 2; mt++)
                #pragma unroll
                for (int nt = 0; nt < 4; nt++) {
                    int pr = nt >> 1, o = nt & 1;
                    float* c = acc[mt][nt];
                    mma_bf16(c[0], c[1], c[2], c[3],
                             ah[mt][0], ah[mt][1], ah[mt][2], ah[mt][3],
                             bh[pr][o], bh[pr][o + 2]);
                    mma_bf16(c[0], c[1], c[2], c[3],
                             ah[mt][0], ah[mt][1], ah[mt][2], ah[mt][3],
                             bl2[pr][o], bl2[pr][o + 2]);
                    mma_bf16(c[0], c[1], c[2], c[3],
                             al2[mt][0], al2[mt][1], al2[mt][2], al2[mt][3],
                             bh[pr][o], bh[pr][o + 2]);
                }
        }
    }

    // ---- store Wh as fp16 ----
    #pragma unroll
    for (int mt = 0; mt < 2; mt++) {
        int r0 = m0 + warp_m + mt * 16 + g;
        int r1 = r0 + 8;
        #pragma unroll
        for (int nt = 0; nt < 4; nt++) {
            int c = n0 + warp_n + nt * 8 + tid * 2;
            if (r0 < NN)
                *(__half2*)&g_Whh[((size_t)p * NN + r0) * HD_ + c] =
                    __floats2half2_rn(acc[mt][nt][0], acc[mt][nt][1]);
            if (r1 < NN)
                *(__half2*)&g_Whh[((size_t)p * NN + r1) * HD_ + c] =
                    __floats2half2_rn(acc[mt][nt][2], acc[mt][nt][3]);
        }
    }

    // ---- fused attention dot-products ----
    int head0 = n0 >> 6;
    int hw = warp_n >= 64;
    int dbase = (warp_n & 32);
    const float* alp = &al[((size_t)p * HH + head0 + hw) * DD];
    const float* arp = &ar[((size_t)p * HH + head0 + hw) * DD];

    s_att[t >> 2][(t >> 1) & 1][t & 1] = 0.f;
    __syncthreads();

    #pragma unroll
    for (int mt = 0; mt < 2; mt++) {
        #pragma unroll
        for (int rr = 0; rr < 2; rr++) {
            float pel = 0.f, per_ = 0.f;
            #pragma unroll
            for (int nt = 0; nt < 4; nt++) {
                #pragma unroll
                for (int j = 0; j < 2; j++) {
                    float c = acc[mt][nt][rr * 2 + j];
                    int dd = dbase + nt * 8 + tid * 2 + j;
                    pel  += c * alp[dd];
                    per_ += c * arp[dd];
                }
            }
            pel  += __shfl_xor_sync(~0u, pel, 1);  pel  += __shfl_xor_sync(~0u, pel, 2);
            per_ += __shfl_xor_sync(~0u, per_, 1); per_ += __shfl_xor_sync(~0u, per_, 2);
            if (tid == 0) {
                int row = warp_m + mt * 16 + g + rr * 8;
                atomicAdd(&s_att[row][hw][0], pel);
                atomicAdd(&s_att[row][hw][1], per_);
            }
        }
    }
    __syncthreads();
    {
        int row = t >> 2, h2 = (t >> 1) & 1, lr = t & 1;
        int gr = m0 + row;
        if (gr < NN) {
            float v = s_att[row][h2][lr];
            size_t idx = ((size_t)p * NN + gr) * HH + head0 + h2;
            if (lr == 0) g_el[idx] = v; else g_er[idx] = v;
        }
    }
}

// ---------------- CSR build ----------------
__global__ void k_count(const int* __restrict__ edst) {
    int e = blockIdx.x * blockDim.x + threadIdx.x;
    int p = blockIdx.y;
    atomicAdd(&g_cnt[p * NN + edst[(size_t)p * EE + e]], 1);
}

__global__ __launch_bounds__(1024) void k_scan() {
    __shared__ int part[1024];
    int p = blockIdx.x;
    int t = threadIdx.x;
    const int CH = 10;
    int b = t * CH;
    int loc[CH];
    int sum = 0;
    #pragma unroll
    for (int i = 0; i < CH; i++) {
        int idx = b + i;
        int v = (idx < NN) ? g_cnt[p * NN + idx] : 0;
        loc[i] = sum;
        sum += v;
    }
    part[t] = sum;
    __syncthreads();
    for (int ofs = 1; ofs < 1024; ofs <<= 1) {
        int val = (t >= ofs) ? part[t - ofs] : 0;
        __syncthreads();
        part[t] += val;
        __syncthreads();
    }
    int ex = part[t] - sum;
    #pragma unroll
    for (int i = 0; i < CH; i++) {
        int idx = b + i;
        if (idx < NN) {
            int o = ex + loc[i];
            g_off[p * NN + idx] = o;
            g_pos[p * NN + idx] = o;
        }
    }
}

__global__ void k_scatter(const int* __restrict__ esrc, const int* __restrict__ edst) {
    int e = blockIdx.x * blockDim.x + threadIdx.x;
    int p = blockIdx.y;
    int d = edst[(size_t)p * EE + e];
    int s = esrc[(size_t)p * EE + e];
    int pos = atomicAdd(&g_pos[p * NN + d], 1);
    g_sperm[(size_t)p * EE + pos] = s;
}

// ---------------- K4: gather, fused softmax, fp16 in/out ----------------
__global__ __launch_bounds__(256) void k_gather(const float* __restrict__ gb) {
    int lane = threadIdx.x & 31;
    int d = blockIdx.x * 8 + (threadIdx.x >> 5);
    if (d >= NN) return;                       // OOB guard
    int p = blockIdx.y;
    int head = lane >> 2;

    int start = g_off[p * NN + d];
    int deg   = g_cnt[p * NN + d];
    const int*    sp  = &g_sperm[(size_t)p * EE + start];
    const float*  elb = &g_el[(size_t)p * NN * HH + head];
    const __half* whb = &g_Whh[(size_t)p * NN * HD_ + lane * 16];
    float erd = g_er[((size_t)p * NN + d) * HH + head];

    float acc[16];
    #pragma unroll
    for (int q = 0; q < 16; q++) acc[q] = 0.f;
    float ssum = 0.f;

    int j = 0;
    for (; j + 3 < deg; j += 4) {
        int s[4];
        #pragma unroll
        for (int u = 0; u < 4; u++) s[u] = sp[j + u];
        float e[4];
        #pragma unroll
        for (int u = 0; u < 4; u++) e[u] = elb[(size_t)s[u] * HH];
        uint4 lo[4], hi[4];
        #pragma unroll
        for (int u = 0; u < 4; u++) {
            const uint4* R = (const uint4*)&whb[(size_t)s[u] * HD_];
            lo[u] = R[0];
            hi[u] = R[1];
        }
        #pragma unroll
        for (int u = 0; u < 4; u++) {
            float xv = edge_exp(e[u], erd);
            ssum += xv;
            acc_h8(acc,     lo[u], xv);
            acc_h8(acc + 8, hi[u], xv);
        }
    }
    for (; j < deg; j++) {
        int s0 = sp[j];
        float xv = edge_exp(elb[(size_t)s0 * HH], erd);
        const uint4* R = (const uint4*)&whb[(size_t)s0 * HD_];
        uint4 a0 = R[0], a1 = R[1];
        ssum += xv;
        acc_h8(acc, a0, xv);  acc_h8(acc + 8, a1, xv);
    }

    float inv = (ssum > 0.f) ? 1.f / ssum : 0.f;
    const float* bp = &gb[p * HD_ + lane * 16];
    float o[16];
    #pragma unroll
    for (int q = 0; q < 4; q++) {
        float4 b4 = *(const float4*)&bp[q * 4];
        o[4*q+0] = acc[4*q+0] * inv + b4.x;
        o[4*q+1] = acc[4*q+1] * inv + b4.y;
        o[4*q+2] = acc[4*q+2] * inv + b4.z;
        o[4*q+3] = acc[4*q+3] * inv + b4.w;
    }
    #pragma unroll
    for (int q = 0; q < 16; q++) o[q] = o[q] > 0.f ? o[q] : expm1f(o[q]);
    uint4* dst = (uint4*)&g_zh[((size_t)p * NN + d) * HD_ + lane * 16];
    __stcs(dst,     pack_h8(o));
    __stcs(dst + 1, pack_h8(o + 8));
}

// ---------------- K5: semantic partial (fp16 z reads, float4 smem) ----------------
#define POST_NB 32
#define W1T_LD 68
#define POST_SMEM ((POST_NB * HD_ + 64 * W1T_LD + 256) * sizeof(float))
__global__ __launch_bounds__(256) void k_post(const float* __restrict__ W1,
                                              const float* __restrict__ b1,
                                              const float* __restrict__ W2) {
    extern __shared__ float dsm[];
    float* zs  = dsm;
    float* w1t = dsm + POST_NB * HD_;
    float* red = w1t + 64 * W1T_LD;
    int p  = blockIdx.y;
    int n0 = blockIdx.x * POST_NB;
    int t  = threadIdx.x;
    for (int i = t; i < POST_NB * HD_ / 8; i += 256) {
        int node = i >> 6, c8 = (i & 63) * 8;
        int gn = n0 + node;
        if (gn < NN) {
            uint4 u = *(const uint4*)&g_zh[((size_t)p * NN + gn) * HD_ + c8];
            float2 f0 = __half22float2(*(__half2*)&u.x);
            float2 f1 = __half22float2(*(__half2*)&u.y);
            float2 f2 = __half22float2(*(__half2*)&u.z);
            float2 f3 = __half22float2(*(__half2*)&u.w);
            *(float4*)&zs[node * HD_ + c8]     = make_float4(f0.x, f0.y, f1.x, f1.y);
            *(float4*)&zs[node * HD_ + c8 + 4] = make_float4(f2.x, f2.y, f3.x, f3.y);
        } else {
            *(float4*)&zs[node * HD_ + c8]     = make_float4(0.f, 0.f, 0.f, 0.f);
            *(float4*)&zs[node * HD_ + c8 + 4] = make_float4(0.f, 0.f, 0.f, 0.f);
        }
    }
    __syncthreads();
    int j = t & 63, grp = t >> 6;
    float acc[8];
    #pragma unroll
    for (int u = 0; u < 8; u++) acc[u] = 0.f;
    for (int kc = 0; kc < 8; kc++) {
        for (int i = t; i < 4096; i += 256) {
            int k = i >> 6, jj = i & 63;
            w1t[jj * W1T_LD + k] = W1[(size_t)(kc * 64 + k) * 64 + jj];
        }
        __syncthreads();
        #pragma unroll 4
        for (int k4 = 0; k4 < 64; k4 += 4) {
            float4 wv = *(const float4*)&w1t[j * W1T_LD + k4];
            int zb = kc * 64 + k4;
            #pragma unroll
            for (int u = 0; u < 8; u++) {
                float4 zv = *(const float4*)&zs[(grp * 8 + u) * HD_ + zb];
                acc[u] += zv.x * wv.x + zv.y * wv.y + zv.z * wv.z + zv.w * wv.w;
            }
        }
        __syncthreads();
    }
    float b = b1[j], w2 = W2[j];
    float contrib = 0.f;
    #pragma unroll
    for (int u = 0; u < 8; u++) {
        int gn = n0 + grp * 8 + u;
        if (gn < NN) contrib += tanhf(acc[u] + b) * w2;
    }
    red[t] = contrib;
    __syncthreads();
    for (int ofs = 128; ofs > 0; ofs >>= 1) {
        if (t < ofs) red[t] += red[t + ofs];
        __syncthreads();
    }
    if (t == 0) atomicAdd(&g_w[p], red[0]);
}

// ---------------- K6: beta ----------------
__global__ void k_beta() {
    if (threadIdx.x == 0) {
        float w[PP], m = -1e30f;
        #pragma unroll
        for (int p = 0; p < PP; p++) { w[p] = g_w[p] / (float)NN; m = fmaxf(m, w[p]); }
        float s = 0.f;
        #pragma unroll
        for (int p = 0; p < PP; p++) { w[p] = expf(w[p] - m); s += w[p]; }
        #pragma unroll
        for (int p = 0; p < PP; p++) g_beta[p] = w[p] / s;
    }
}

// ---------------- K7: combine (fp16 z reads) ----------------
__global__ void k_comb(float* __restrict__ out) {
    int i = blockIdx.x * blockDim.x + threadIdx.x;   // 8-elem chunk index
    const size_t stride = (size_t)NN * HD_;
    float bw[PP] = {g_beta[0], g_beta[1], g_beta[2], g_beta[3]};
    float o[8] = {0,0,0,0,0,0,0,0};
    #pragma unroll
    for (int p = 0; p < PP; p++) {
        uint4 u = *(const uint4*)&g_zh[p * stride + (size_t)i * 8];
        float2 f0 = __half22float2(*(__half2*)&u.x);
        float2 f1 = __half22float2(*(__half2*)&u.y);
        float2 f2 = __half22float2(*(__half2*)&u.z);
        float2 f3 = __half22float2(*(__half2*)&u.w);
        o[0] += bw[p] * f0.x;  o[1] += bw[p] * f0.y;
        o[2] += bw[p] * f1.x;  o[3] += bw[p] * f1.y;
        o[4] += bw[p] * f2.x;  o[5] += bw[p] * f2.y;
        o[6] += bw[p] * f3.x;  o[7] += bw[p] * f3.y;
    }
    *(float4*)&out[(size_t)i * 8]     = make_float4(o[0], o[1], o[2], o[3]);
    *(float4*)&out[(size_t)i * 8 + 4] = make_float4(o[4], o[5], o[6], o[7]);
}

// ---------------- launcher ----------------
extern "C" void kernel_launch(void* const* d_in, const int* in_sizes, int n_in,
                              void* d_out, int out_size) {
    const float* h     = (const float*)d_in[0];
    const int*   esrc  = (const int*)  d_in[1];
    const int*   edst  = (const int*)  d_in[2];
    const float* gat_W = (const float*)d_in[3];
    const float* al    = (const float*)d_in[4];
    const float* ar    = (const float*)d_in[5];
    const float* gat_b = (const float*)d_in[6];
    const float* sW1   = (const float*)d_in[7];
    const float* sb1   = (const float*)d_in[8];
    const float* sW2   = (const float*)d_in[9];
    float* out = (float*)d_out;

    cudaFuncSetAttribute(k_post, cudaFuncAttributeMaxDynamicSharedMemorySize,
                         (int)POST_SMEM);

    k_zero<<<(PP * NN + 255) / 256, 256>>>();
    k_cvt_h<<<(NN * INF_ + 255) / 256, 256>>>(h);
    dim3 gw(INF_ / 32, HD_ / 32, PP);
    k_cvt_W<<<gw, dim3(32, 8)>>>(gat_W);

    // launch #4 — gemm (profiled by ncu)
    dim3 gg((NN + 63) / 64, HD_ / 128, PP);
    k_gemm<<<gg, 256>>>(al, ar);

    dim3 ge(EE / 256, PP);
    k_count<<<ge, 256>>>(edst);
    k_scan<<<PP, 1024>>>();
    k_scatter<<<ge, 256>>>(esrc, edst);

    dim3 gga((NN + 7) / 8, PP);
    k_gather<<<gga, 256>>>(gat_b);

    dim3 gp((NN + POST_NB - 1) / POST_NB, PP);
    k_post<<<gp, 256, POST_SMEM>>>(sW1, sb1, sW2);

    k_beta<<<1, 32>>>();

    k_comb<<<(NN * HD_ / 8) / 256, 256>>>(out);
}

// round 17
// speedup vs baseline: 1.0796x; 1.0441x over previous
#include <cuda_runtime.h>
#include <cuda_bf16.h>
#include <cuda_fp16.h>
#include <cstdint>

#define NN   10000
#define NPAD 10048          // 157*64
#define PP   4
#define EE   160000
#define INF_ 256
#define HH   8
#define DD   64
#define HD_  512
#define NEG_SLOPE 0.2f

// ---------------- device scratch ----------------
__device__ __half g_Whh[(size_t)PP * NN * HD_];   // fp16 Wh (gather input)
__device__ __half g_zh[(size_t)PP * NN * HD_];    // fp16 z (gather output)
__device__ float g_el[(size_t)PP * NN * HH];
__device__ float g_er[(size_t)PP * NN * HH];
__device__ int   g_cnt[PP * NN];
__device__ int   g_off[PP * NN];
__device__ int   g_pos[PP * NN];
__device__ int   g_sperm[(size_t)PP * EE];
__device__ __nv_bfloat16 g_h_hi[(size_t)NPAD * INF_];   // pad rows stay zero
__device__ __nv_bfloat16 g_h_lo[(size_t)NPAD * INF_];
__device__ __nv_bfloat16 g_W_hi[(size_t)PP * HD_ * INF_];  // [p][n][k]
__device__ __nv_bfloat16 g_W_lo[(size_t)PP * HD_ * INF_];
__device__ float g_w [PP];
__device__ float g_beta[PP];

// ---------------- K0 ----------------
__global__ void k_zero() {
    int i = blockIdx.x * blockDim.x + threadIdx.x;
    if (i < PP * NN) g_cnt[i] = 0;
    if (i < PP) g_w[i] = 0.f;
}

// ---------------- convert h to bf16 hi/lo ----------------
__global__ void k_cvt_h(const float* __restrict__ h) {
    int i = blockIdx.x * blockDim.x + threadIdx.x;
    if (i < NN * INF_) {
        float v = h[i];
        __nv_bfloat16 hi = __float2bfloat16(v);
        g_h_hi[i] = hi;
        g_h_lo[i] = __float2bfloat16(v - __bfloat162float(hi));
    }
}

// ---------------- convert + transpose W ----------------
__global__ void k_cvt_W(const float* __restrict__ W) {
    __shared__ float tile[32][33];
    int p  = blockIdx.z;
    int k0 = blockIdx.x * 32;
    int n0 = blockIdx.y * 32;
    int tx = threadIdx.x, ty0 = threadIdx.y;
    for (int ty = ty0; ty < 32; ty += 8)
        tile[ty][tx] = W[(size_t)p * INF_ * HD_ + (size_t)(k0 + ty) * HD_ + n0 + tx];
    __syncthreads();
    for (int ty = ty0; ty < 32; ty += 8) {
        float v = tile[tx][ty];
        __nv_bfloat16 hi = __float2bfloat16(v);
        size_t oi = (size_t)p * HD_ * INF_ + (size_t)(n0 + ty) * INF_ + k0 + tx;
        g_W_hi[oi] = hi;
        g_W_lo[oi] = __float2bfloat16(v - __bfloat162float(hi));
    }
}

// ---------------- gather math helpers ----------------
__device__ __forceinline__ void acc_h8(float* acc, uint4 u, float xv) {
    float2 f0 = __half22float2(*(__half2*)&u.x);
    float2 f1 = __half22float2(*(__half2*)&u.y);
    float2 f2 = __half22float2(*(__half2*)&u.z);
    float2 f3 = __half22float2(*(__half2*)&u.w);
    acc[0] += xv * f0.x;  acc[1] += xv * f0.y;
    acc[2] += xv * f1.x;  acc[3] += xv * f1.y;
    acc[4] += xv * f2.x;  acc[5] += xv * f2.y;
    acc[6] += xv * f3.x;  acc[7] += xv * f3.y;
}
__device__ __forceinline__ float edge_exp(float el, float erd) {
    float v = el + erd;
    v = v > 0.f ? v : NEG_SLOPE * v;
    return expf(v);       // shift-free softmax (safe range)
}
__device__ __forceinline__ uint4 pack_h8(const float* o) {
    uint4 r;
    *(__half2*)&r.x = __floats2half2_rn(o[0], o[1]);
    *(__half2*)&r.y = __floats2half2_rn(o[2], o[3]);
    *(__half2*)&r.z = __floats2half2_rn(o[4], o[5]);
    *(__half2*)&r.w = __floats2half2_rn(o[6], o[7]);
    return r;
}

// ---------------- mma / ldmatrix helpers ----------------
__device__ __forceinline__ void mma_bf16(float& c0, float& c1, float& c2, float& c3,
                                         uint32_t a0, uint32_t a1, uint32_t a2, uint32_t a3,
                                         uint32_t b0, uint32_t b1) {
    asm volatile("mma.sync.aligned.m16n8k16.row.col.f32.bf16.bf16.f32 "
                 "{%0,%1,%2,%3}, {%4,%5,%6,%7}, {%8,%9}, {%0,%1,%2,%3};"
                 : "+f"(c0), "+f"(c1), "+f"(c2), "+f"(c3)
                 : "r"(a0), "r"(a1), "r"(a2), "r"(a3), "r"(b0), "r"(b1));
}
__device__ __forceinline__ void ldsm4(uint32_t* r, const void* ptr) {
    uint32_t a = (uint32_t)__cvta_generic_to_shared(ptr);
    asm volatile("ldmatrix.sync.aligned.m8n8.x4.shared.b16 {%0,%1,%2,%3}, [%4];"
                 : "=r"(r[0]), "=r"(r[1]), "=r"(r[2]), "=r"(r[3]) : "r"(a));
}

// ---------------- K1: Wh = h @ W[p] (bf16 hi/lo 3-term mma.sync) + fused el/er ------
__global__ __launch_bounds__(256) void k_gemm(const float* __restrict__ al,
                                              const float* __restrict__ ar) {
    __shared__ __nv_bfloat16 As_hi[64][40];
    __shared__ __nv_bfloat16 As_lo[64][40];
    __shared__ __nv_bfloat16 Bs_hi[128][40];
    __shared__ __nv_bfloat16 Bs_lo[128][40];
    __shared__ float s_att[64][2][2];

    int p  = blockIdx.z;
    int m0 = blockIdx.x * 64;
    int n0 = blockIdx.y * 128;
    int t    = threadIdx.x;
    int lane = t & 31;
    int w    = t >> 5;
    int warp_m = (w & 1) * 32;
    int warp_n = (w >> 1) * 32;
    int g   = lane >> 2;
    int tid = lane & 3;
    int lm_r = lane & 15;
    int lm_c = (lane >> 4) * 8;

    float acc[2][4][4];
    #pragma unroll
    for (int mt = 0; mt < 2; mt++)
        #pragma unroll
        for (int nt = 0; nt < 4; nt++)
            #pragma unroll
            for (int q = 0; q < 4; q++) acc[mt][nt][q] = 0.f;

    int a_row  = t >> 2;
    int a_koff = (t & 3) * 8;
    const __nv_bfloat16* ah_base  = &g_h_hi[(size_t)(m0 + a_row) * INF_ + a_koff];
    const __nv_bfloat16* alo_base = &g_h_lo[(size_t)(m0 + a_row) * INF_ + a_koff];
    int b_n0 = t >> 2;
    int b_k0 = (t & 3) * 8;
    int b_n1 = (t + 256) >> 2;
    int b_k1 = ((t + 256) & 3) * 8;
    const __nv_bfloat16* bW  = &g_W_hi[(size_t)p * HD_ * INF_ + (size_t)n0 * INF_];
    const __nv_bfloat16* bWl = &g_W_lo[(size_t)p * HD_ * INF_ + (size_t)n0 * INF_];

    uint4 pa_hi, pa_lo, pb_hi0, pb_hi1, pb_lo0, pb_lo1;
    pa_hi  = *(const uint4*)&ah_base[0];
    pa_lo  = *(const uint4*)&alo_base[0];
    pb_hi0 = *(const uint4*)&bW [(size_t)b_n0 * INF_ + b_k0];
    pb_hi1 = *(const uint4*)&bW [(size_t)b_n1 * INF_ + b_k1];
    pb_lo0 = *(const uint4*)&bWl[(size_t)b_n0 * INF_ + b_k0];
    pb_lo1 = *(const uint4*)&bWl[(size_t)b_n1 * INF_ + b_k1];

    for (int kb = 0; kb < 8; kb++) {
        __syncthreads();
        *(uint4*)&As_hi[a_row][a_koff] = pa_hi;
        *(uint4*)&As_lo[a_row][a_koff] = pa_lo;
        *(uint4*)&Bs_hi[b_n0][b_k0]    = pb_hi0;
        *(uint4*)&Bs_hi[b_n1][b_k1]    = pb_hi1;
        *(uint4*)&Bs_lo[b_n0][b_k0]    = pb_lo0;
        *(uint4*)&Bs_lo[b_n1][b_k1]    = pb_lo1;
        __syncthreads();
        if (kb < 7) {
            int kk = (kb + 1) * 32;
            pa_hi  = *(const uint4*)&ah_base[kk];
            pa_lo  = *(const uint4*)&alo_base[kk];
            pb_hi0 = *(const uint4*)&bW [(size_t)b_n0 * INF_ + kk + b_k0];
            pb_hi1 = *(const uint4*)&bW [(size_t)b_n1 * INF_ + kk + b_k1];
            pb_lo0 = *(const uint4*)&bWl[(size_t)b_n0 * INF_ + kk + b_k0];
            pb_lo1 = *(const uint4*)&bWl[(size_t)b_n1 * INF_ + kk + b_k1];
        }
        #pragma unroll
        for (int ks = 0; ks < 32; ks += 16) {
            uint32_t ah[2][4], al2[2][4], bh[2][4], bl2[2][4];
            #pragma unroll
            for (int mt = 0; mt < 2; mt++) {
                ldsm4(ah[mt],  &As_hi[warp_m + mt * 16 + lm_r][ks + lm_c]);
                ldsm4(al2[mt], &As_lo[warp_m + mt * 16 + lm_r][ks + lm_c]);
            }
            #pragma unroll
            for (int pr = 0; pr < 2; pr++) {
                ldsm4(bh[pr],  &Bs_hi[warp_n + pr * 16 + lm_r][ks + lm_c]);
                ldsm4(bl2[pr], &Bs_lo[warp_n + pr * 16 + lm_r][ks + lm_c]);
            }
            #pragma unroll
            for (int mt = 0; mt < 2; mt++)
                #pragma unroll
                for (int nt = 0; nt < 4; nt++) {
                    int pr = nt >> 1, o = nt & 1;
                    float* c = acc[mt][nt];
                    mma_bf16(c[0], c[1], c[2], c[3],
                             ah[mt][0], ah[mt][1], ah[mt][2], ah[mt][3],
                             bh[pr][o], bh[pr][o + 2]);
                    mma_bf16(c[0], c[1], c[2], c[3],
                             ah[mt][0], ah[mt][1], ah[mt][2], ah[mt][3],
                             bl2[pr][o], bl2[pr][o + 2]);
                    mma_bf16(c[0], c[1], c[2], c[3],
                             al2[mt][0], al2[mt][1], al2[mt][2], al2[mt][3],
                             bh[pr][o], bh[pr][o + 2]);
                }
        }
    }

    // ---- store Wh as fp16 ----
    #pragma unroll
    for (int mt = 0; mt < 2; mt++) {
        int r0 = m0 + warp_m + mt * 16 + g;
        int r1 = r0 + 8;
        #pragma unroll
        for (int nt = 0; nt < 4; nt++) {
            int c = n0 + warp_n + nt * 8 + tid * 2;
            if (r0 < NN)
                *(__half2*)&g_Whh[((size_t)p * NN + r0) * HD_ + c] =
                    __floats2half2_rn(acc[mt][nt][0], acc[mt][nt][1]);
            if (r1 < NN)
                *(__half2*)&g_Whh[((size_t)p * NN + r1) * HD_ + c] =
                    __floats2half2_rn(acc[mt][nt][2], acc[mt][nt][3]);
        }
    }

    // ---- fused attention dot-products ----
    int head0 = n0 >> 6;
    int hw = warp_n >= 64;
    int dbase = (warp_n & 32);
    const float* alp = &al[((size_t)p * HH + head0 + hw) * DD];
    const float* arp = &ar[((size_t)p * HH + head0 + hw) * DD];

    s_att[t >> 2][(t >> 1) & 1][t & 1] = 0.f;
    __syncthreads();

    #pragma unroll
    for (int mt = 0; mt < 2; mt++) {
        #pragma unroll
        for (int rr = 0; rr < 2; rr++) {
            float pel = 0.f, per_ = 0.f;
            #pragma unroll
            for (int nt = 0; nt < 4; nt++) {
                #pragma unroll
                for (int j = 0; j < 2; j++) {
                    float c = acc[mt][nt][rr * 2 + j];
                    int dd = dbase + nt * 8 + tid * 2 + j;
                    pel  += c * alp[dd];
                    per_ += c * arp[dd];
                }
            }
            pel  += __shfl_xor_sync(~0u, pel, 1);  pel  += __shfl_xor_sync(~0u, pel, 2);
            per_ += __shfl_xor_sync(~0u, per_, 1); per_ += __shfl_xor_sync(~0u, per_, 2);
            if (tid == 0) {
                int row = warp_m + mt * 16 + g + rr * 8;
                atomicAdd(&s_att[row][hw][0], pel);
                atomicAdd(&s_att[row][hw][1], per_);
            }
        }
    }
    __syncthreads();
    {
        int row = t >> 2, h2 = (t >> 1) & 1, lr = t & 1;
        int gr = m0 + row;
        if (gr < NN) {
            float v = s_att[row][h2][lr];
            size_t idx = ((size_t)p * NN + gr) * HH + head0 + h2;
            if (lr == 0) g_el[idx] = v; else g_er[idx] = v;
        }
    }
}

// ---------------- CSR build ----------------
__global__ void k_count(const int* __restrict__ edst) {
    int e = blockIdx.x * blockDim.x + threadIdx.x;
    int p = blockIdx.y;
    atomicAdd(&g_cnt[p * NN + edst[(size_t)p * EE + e]], 1);
}

__global__ __launch_bounds__(1024) void k_scan() {
    __shared__ int part[1024];
    int p = blockIdx.x;
    int t = threadIdx.x;
    const int CH = 10;
    int b = t * CH;
    int loc[CH];
    int sum = 0;
    #pragma unroll
    for (int i = 0; i < CH; i++) {
        int idx = b + i;
        int v = (idx < NN) ? g_cnt[p * NN + idx] : 0;
        loc[i] = sum;
        sum += v;
    }
    part[t] = sum;
    __syncthreads();
    for (int ofs = 1; ofs < 1024; ofs <<= 1) {
        int val = (t >= ofs) ? part[t - ofs] : 0;
        __syncthreads();
        part[t] += val;
        __syncthreads();
    }
    int ex = part[t] - sum;
    #pragma unroll
    for (int i = 0; i < CH; i++) {
        int idx = b + i;
        if (idx < NN) {
            int o = ex + loc[i];
            g_off[p * NN + idx] = o;
            g_pos[p * NN + idx] = o;
        }
    }
}

__global__ void k_scatter(const int* __restrict__ esrc, const int* __restrict__ edst) {
    int e = blockIdx.x * blockDim.x + threadIdx.x;
    int p = blockIdx.y;
    int d = edst[(size_t)p * EE + e];
    int s = esrc[(size_t)p * EE + e];
    int pos = atomicAdd(&g_pos[p * NN + d], 1);
    g_sperm[(size_t)p * EE + pos] = s;
}

// ---------------- K4: gather, ONE WARP PER CTA (independent retirement) ----------
__global__ __launch_bounds__(32) void k_gather(const float* __restrict__ gb) {
    int lane = threadIdx.x;
    int d = blockIdx.x;
    int p = blockIdx.y;
    int head = lane >> 2;

    int start = g_off[p * NN + d];
    int deg   = g_cnt[p * NN + d];
    const int*    sp  = &g_sperm[(size_t)p * EE + start];
    const float*  elb = &g_el[(size_t)p * NN * HH + head];
    const __half* whb = &g_Whh[(size_t)p * NN * HD_ + lane * 16];
    float erd = g_er[((size_t)p * NN + d) * HH + head];

    float acc[16];
    #pragma unroll
    for (int q = 0; q < 16; q++) acc[q] = 0.f;
    float ssum = 0.f;

    int j = 0;
    for (; j + 3 < deg; j += 4) {
        int s[4];
        #pragma unroll
        for (int u = 0; u < 4; u++) s[u] = sp[j + u];
        float e[4];
        #pragma unroll
        for (int u = 0; u < 4; u++) e[u] = elb[(size_t)s[u] * HH];
        uint4 lo[4], hi[4];
        #pragma unroll
        for (int u = 0; u < 4; u++) {
            const uint4* R = (const uint4*)&whb[(size_t)s[u] * HD_];
            lo[u] = R[0];
            hi[u] = R[1];
        }
        #pragma unroll
        for (int u = 0; u < 4; u++) {
            float xv = edge_exp(e[u], erd);
            ssum += xv;
            acc_h8(acc,     lo[u], xv);
            acc_h8(acc + 8, hi[u], xv);
        }
    }
    for (; j < deg; j++) {
        int s0 = sp[j];
        float xv = edge_exp(elb[(size_t)s0 * HH], erd);
        const uint4* R = (const uint4*)&whb[(size_t)s0 * HD_];
        uint4 a0 = R[0], a1 = R[1];
        ssum += xv;
        acc_h8(acc, a0, xv);  acc_h8(acc + 8, a1, xv);
    }

    float inv = (ssum > 0.f) ? 1.f / ssum : 0.f;
    const float* bp = &gb[p * HD_ + lane * 16];
    float o[16];
    #pragma unroll
    for (int q = 0; q < 4; q++) {
        float4 b4 = *(const float4*)&bp[q * 4];
        o[4*q+0] = acc[4*q+0] * inv + b4.x;
        o[4*q+1] = acc[4*q+1] * inv + b4.y;
        o[4*q+2] = acc[4*q+2] * inv + b4.z;
        o[4*q+3] = acc[4*q+3] * inv + b4.w;
    }
    #pragma unroll
    for (int q = 0; q < 16; q++) o[q] = o[q] > 0.f ? o[q] : expm1f(o[q]);
    uint4* dst = (uint4*)&g_zh[((size_t)p * NN + d) * HD_ + lane * 16];
    __stcs(dst,     pack_h8(o));
    __stcs(dst + 1, pack_h8(o + 8));
}

// ---------------- K5: semantic partial (fp16 z reads, float4 smem) ----------------
#define POST_NB 32
#define W1T_LD 68
#define POST_SMEM ((POST_NB * HD_ + 64 * W1T_LD + 256) * sizeof(float))
__global__ __launch_bounds__(256) void k_post(const float* __restrict__ W1,
                                              const float* __restrict__ b1,
                                              const float* __restrict__ W2) {
    extern __shared__ float dsm[];
    float* zs  = dsm;
    float* w1t = dsm + POST_NB * HD_;
    float* red = w1t + 64 * W1T_LD;
    int p  = blockIdx.y;
    int n0 = blockIdx.x * POST_NB;
    int t  = threadIdx.x;
    for (int i = t; i < POST_NB * HD_ / 8; i += 256) {
        int node = i >> 6, c8 = (i & 63) * 8;
        int gn = n0 + node;
        if (gn < NN) {
            uint4 u = *(const uint4*)&g_zh[((size_t)p * NN + gn) * HD_ + c8];
            float2 f0 = __half22float2(*(__half2*)&u.x);
            float2 f1 = __half22float2(*(__half2*)&u.y);
            float2 f2 = __half22float2(*(__half2*)&u.z);
            float2 f3 = __half22float2(*(__half2*)&u.w);
            *(float4*)&zs[node * HD_ + c8]     = make_float4(f0.x, f0.y, f1.x, f1.y);
            *(float4*)&zs[node * HD_ + c8 + 4] = make_float4(f2.x, f2.y, f3.x, f3.y);
        } else {
            *(float4*)&zs[node * HD_ + c8]     = make_float4(0.f, 0.f, 0.f, 0.f);
            *(float4*)&zs[node * HD_ + c8 + 4] = make_float4(0.f, 0.f, 0.f, 0.f);
        }
    }
    __syncthreads();
    int j = t & 63, grp = t >> 6;
    float acc[8];
    #pragma unroll
    for (int u = 0; u < 8; u++) acc[u] = 0.f;
    for (int kc = 0; kc < 8; kc++) {
        for (int i = t; i < 4096; i += 256) {
            int k = i >> 6, jj = i & 63;
            w1t[jj * W1T_LD + k] = W1[(size_t)(kc * 64 + k) * 64 + jj];
        }
        __syncthreads();
        #pragma unroll 4
        for (int k4 = 0; k4 < 64; k4 += 4) {
            float4 wv = *(const float4*)&w1t[j * W1T_LD + k4];
            int zb = kc * 64 + k4;
            #pragma unroll
            for (int u = 0; u < 8; u++) {
                float4 zv = *(const float4*)&zs[(grp * 8 + u) * HD_ + zb];
                acc[u] += zv.x * wv.x + zv.y * wv.y + zv.z * wv.z + zv.w * wv.w;
            }
        }
        __syncthreads();
    }
    float b = b1[j], w2 = W2[j];
    float contrib = 0.f;
    #pragma unroll
    for (int u = 0; u < 8; u++) {
        int gn = n0 + grp * 8 + u;
        if (gn < NN) contrib += tanhf(acc[u] + b) * w2;
    }
    red[t] = contrib;
    __syncthreads();
    for (int ofs = 128; ofs > 0; ofs >>= 1) {
        if (t < ofs) red[t] += red[t + ofs];
        __syncthreads();
    }
    if (t == 0) atomicAdd(&g_w[p], red[0]);
}

// ---------------- K6: beta ----------------
__global__ void k_beta() {
    if (threadIdx.x == 0) {
        float w[PP], m = -1e30f;
        #pragma unroll
        for (int p = 0; p < PP; p++) { w[p] = g_w[p] / (float)NN; m = fmaxf(m, w[p]); }
        float s = 0.f;
        #pragma unroll
        for (int p = 0; p < PP; p++) { w[p] = expf(w[p] - m); s += w[p]; }
        #pragma unroll
        for (int p = 0; p < PP; p++) g_beta[p] = w[p] / s;
    }
}

// ---------------- K7: combine (fp16 z reads) ----------------
__global__ void k_comb(float* __restrict__ out) {
    int i = blockIdx.x * blockDim.x + threadIdx.x;   // 8-elem chunk index
    const size_t stride = (size_t)NN * HD_;
    float bw[PP] = {g_beta[0], g_beta[1], g_beta[2], g_beta[3]};
    float o[8] = {0,0,0,0,0,0,0,0};
    #pragma unroll
    for (int p = 0; p < PP; p++) {
        uint4 u = *(const uint4*)&g_zh[p * stride + (size_t)i * 8];
        float2 f0 = __half22float2(*(__half2*)&u.x);
        float2 f1 = __half22float2(*(__half2*)&u.y);
        float2 f2 = __half22float2(*(__half2*)&u.z);
        float2 f3 = __half22float2(*(__half2*)&u.w);
        o[0] += bw[p] * f0.x;  o[1] += bw[p] * f0.y;
        o[2] += bw[p] * f1.x;  o[3] += bw[p] * f1.y;
        o[4] += bw[p] * f2.x;  o[5] += bw[p] * f2.y;
        o[6] += bw[p] * f3.x;  o[7] += bw[p] * f3.y;
    }
    *(float4*)&out[(size_t)i * 8]     = make_float4(o[0], o[1], o[2], o[3]);
    *(float4*)&out[(size_t)i * 8 + 4] = make_float4(o[4], o[5], o[6], o[7]);
}

// ---------------- launcher ----------------
extern "C" void kernel_launch(void* const* d_in, const int* in_sizes, int n_in,
                              void* d_out, int out_size) {
    const float* h     = (const float*)d_in[0];
    const int*   esrc  = (const int*)  d_in[1];
    const int*   edst  = (const int*)  d_in[2];
    const float* gat_W = (const float*)d_in[3];
    const float* al    = (const float*)d_in[4];
    const float* ar    = (const float*)d_in[5];
    const float* gat_b = (const float*)d_in[6];
    const float* sW1   = (const float*)d_in[7];
    const float* sb1   = (const float*)d_in[8];
    const float* sW2   = (const float*)d_in[9];
    float* out = (float*)d_out;

    cudaFuncSetAttribute(k_post, cudaFuncAttributeMaxDynamicSharedMemorySize,
                         (int)POST_SMEM);

    k_zero<<<(PP * NN + 255) / 256, 256>>>();
    k_cvt_h<<<(NN * INF_ + 255) / 256, 256>>>(h);
    dim3 gw(INF_ / 32, HD_ / 32, PP);
    k_cvt_W<<<gw, dim3(32, 8)>>>(gat_W);

    // launch #4 — gemm (profiled by ncu, control)
    dim3 gg((NN + 63) / 64, HD_ / 128, PP);
    k_gemm<<<gg, 256>>>(al, ar);

    dim3 ge(EE / 256, PP);
    k_count<<<ge, 256>>>(edst);
    k_scan<<<PP, 1024>>>();
    k_scatter<<<ge, 256>>>(esrc, edst);

    // one warp per node -> independent warp retirement, no CTA-max imbalance
    dim3 gga(NN, PP);
    k_gather<<<gga, 32>>>(gat_b);

    dim3 gp((NN + POST_NB - 1) / POST_NB, PP);
    k_post<<<gp, 256, POST_SMEM>>>(sW1, sb1, sW2);

    k_beta<<<1, 32>>>();

    k_comb<<<(NN * HD_ / 8) / 256, 256>>>(out);
}